// round 1
// baseline (speedup 1.0000x reference)
#include <cuda_runtime.h>
#include <math.h>

#define D_MODEL 1024
#define L_SEQ   2048
#define BATCH   4
#define NHEADS  16
#define DK      64
#define ROWS    (BATCH * L_SEQ)   /* 8192 */

/* ---------------- scratch (static device globals; no allocations) -------- */
__device__ float g_xn  [ (size_t)ROWS * D_MODEL ];        /* 32 MB  */
__device__ float g_qkv [ (size_t)ROWS * 3 * D_MODEL ];    /* 96 MB  */
__device__ float g_attn[ (size_t)ROWS * D_MODEL ];        /* 32 MB  */

/* ---------------- LayerNorm: one block per row --------------------------- */
__global__ __launch_bounds__(256) void ln_kernel(
    const float* __restrict__ x, const float* __restrict__ g,
    const float* __restrict__ b, float* __restrict__ out)
{
    int row = blockIdx.x;
    int t   = threadIdx.x;                       /* 256 threads, 256 float4 */
    const float4* xr = (const float4*)(x + (size_t)row * D_MODEL);
    float4 v = xr[t];
    float s  = v.x + v.y + v.z + v.w;
    float sq = v.x*v.x + v.y*v.y + v.z*v.z + v.w*v.w;

    __shared__ float red0[8], red1[8];
    #pragma unroll
    for (int off = 16; off > 0; off >>= 1) {
        s  += __shfl_down_sync(0xffffffffu, s,  off);
        sq += __shfl_down_sync(0xffffffffu, sq, off);
    }
    int warp = t >> 5, lane = t & 31;
    if (lane == 0) { red0[warp] = s; red1[warp] = sq; }
    __syncthreads();
    if (t < 32) {
        float s2 = (t < 8) ? red0[t] : 0.f;
        float q2 = (t < 8) ? red1[t] : 0.f;
        #pragma unroll
        for (int off = 4; off > 0; off >>= 1) {
            s2 += __shfl_down_sync(0xffffffffu, s2, off);
            q2 += __shfl_down_sync(0xffffffffu, q2, off);
        }
        if (t == 0) {
            float mu  = s2 * (1.0f / D_MODEL);
            float var = q2 * (1.0f / D_MODEL) - mu * mu;
            red0[0] = mu;
            red1[0] = rsqrtf(var + 1e-5f);
        }
    }
    __syncthreads();
    float mu = red0[0], rstd = red1[0];
    float4 gv = ((const float4*)g)[t];
    float4 bv = ((const float4*)b)[t];
    float4 o;
    o.x = (v.x - mu) * rstd * gv.x + bv.x;
    o.y = (v.y - mu) * rstd * gv.y + bv.y;
    o.z = (v.z - mu) * rstd * gv.z + bv.z;
    o.w = (v.w - mu) * rstd * gv.w + bv.w;
    ((float4*)(out + (size_t)row * D_MODEL))[t] = o;
}

/* ---------------- 128x128x8 SGEMM, 8x8 per thread, fused bias/residual --- */
template<bool RES>
__global__ __launch_bounds__(256) void sgemm_kernel(
    const float* __restrict__ A, const float* __restrict__ B,
    const float* __restrict__ bias, const float* __restrict__ res,
    float* __restrict__ C, int M, int N, int K)
{
    const int BM = 128, BN = 128, BK = 8;
    __shared__ float As[BK][BM];
    __shared__ float Bs[BK][BN];

    int tid  = threadIdx.x;
    int brow = blockIdx.y * BM;
    int bcol = blockIdx.x * BN;
    int trow = (tid >> 4) * 8;        /* 0..120 */
    int tcol = (tid & 15) * 8;        /* 0..120 */

    float acc[8][8];
    #pragma unroll
    for (int i = 0; i < 8; i++)
        #pragma unroll
        for (int j = 0; j < 8; j++) acc[i][j] = 0.f;

    int arow  = tid >> 1;             /* 0..127 */
    int acol  = (tid & 1) * 4;        /* 0 or 4 */
    int browl = tid >> 5;             /* 0..7   */
    int bcoll = (tid & 31) * 4;       /* 0..124 */

    const float* Aptr = A + (size_t)(brow + arow) * K + acol;
    const float* Bptr = B + (size_t)browl * N + bcol + bcoll;

    for (int k0 = 0; k0 < K; k0 += BK) {
        float4 a = *(const float4*)(Aptr + k0);
        As[acol + 0][arow] = a.x;
        As[acol + 1][arow] = a.y;
        As[acol + 2][arow] = a.z;
        As[acol + 3][arow] = a.w;
        float4 bvv = *(const float4*)(Bptr + (size_t)k0 * N);
        *(float4*)&Bs[browl][bcoll] = bvv;
        __syncthreads();

        #pragma unroll
        for (int kk = 0; kk < BK; kk++) {
            float a0[8], b0[8];
            *(float4*)&a0[0] = *(float4*)&As[kk][trow];
            *(float4*)&a0[4] = *(float4*)&As[kk][trow + 4];
            *(float4*)&b0[0] = *(float4*)&Bs[kk][tcol];
            *(float4*)&b0[4] = *(float4*)&Bs[kk][tcol + 4];
            #pragma unroll
            for (int i = 0; i < 8; i++)
                #pragma unroll
                for (int j = 0; j < 8; j++)
                    acc[i][j] = fmaf(a0[i], b0[j], acc[i][j]);
        }
        __syncthreads();
    }

    float bias0[8];
    *(float4*)&bias0[0] = *(const float4*)&bias[bcol + tcol];
    *(float4*)&bias0[4] = *(const float4*)&bias[bcol + tcol + 4];

    #pragma unroll
    for (int i = 0; i < 8; i++) {
        int gr = brow + trow + i;
        float* Crow = C + (size_t)gr * N + bcol + tcol;
        #pragma unroll
        for (int j = 0; j < 8; j += 4) {
            float4 o;
            o.x = acc[i][j + 0] + bias0[j + 0];
            o.y = acc[i][j + 1] + bias0[j + 1];
            o.z = acc[i][j + 2] + bias0[j + 2];
            o.w = acc[i][j + 3] + bias0[j + 3];
            if (RES) {
                const float* Rrow = res + (size_t)gr * N + bcol + tcol;
                float4 r4 = *(const float4*)(Rrow + j);
                o.x += r4.x; o.y += r4.y; o.z += r4.z; o.w += r4.w;
            }
            *(float4*)(Crow + j) = o;
        }
    }
}

/* ---------------- Flash attention, BR=BC=64, online softmax -------------- */
#define FPAD 68   /* row stride (floats) for 64-wide smem tiles */

__global__ __launch_bounds__(256) void flash_kernel(
    const float* __restrict__ qkv, float* __restrict__ out)
{
    extern __shared__ float sm[];
    float* Qt  = sm;                 /* [d=64][r=64]  Qt[d*FPAD + r]  */
    float* Kt  = Qt + 64 * FPAD;     /* [d=64][c=64]  Kt[d*FPAD + c]  */
    float* Vs  = Kt + 64 * FPAD;     /* [c=64][d=64]  Vs[c*FPAD + d]  */
    float* St  = Vs + 64 * FPAD;     /* [c=64][r=64]  St[c*FPAD + r]  */
    float* m_s  = St + 64 * FPAD;    /* [64] running max   */
    float* l_s  = m_s + 64;          /* [64] running sum   */
    float* sc_s = l_s + 64;          /* [64] rescale       */

    int qt  = blockIdx.x;            /* query tile 0..31 */
    int h   = blockIdx.y;
    int b   = blockIdx.z;
    int tid = threadIdx.x;
    const float scale = 0.125f;      /* 1/sqrt(64) */

    const float* base = qkv + (size_t)b * L_SEQ * 3072 + h * 64;
    /* q row l at base + l*3072 ; k at +1024 ; v at +2048 */

    int lr = tid >> 2;               /* 0..63 : tile row loaded by this thread */
    int db = (tid & 3) * 16;         /* d offset 0/16/32/48 */

    /* load Q tile transposed (d-major), pre-scaled */
    {
        const float* qrow = base + (size_t)(qt * 64 + lr) * 3072 + db;
        #pragma unroll
        for (int v4 = 0; v4 < 4; v4++) {
            float4 q = *(const float4*)(qrow + v4 * 4);
            int d0 = db + v4 * 4;
            Qt[(d0 + 0) * FPAD + lr] = q.x * scale;
            Qt[(d0 + 1) * FPAD + lr] = q.y * scale;
            Qt[(d0 + 2) * FPAD + lr] = q.z * scale;
            Qt[(d0 + 3) * FPAD + lr] = q.w * scale;
        }
    }
    if (tid < 64) { m_s[tid] = -INFINITY; l_s[tid] = 0.f; }

    int tx4 = (tid & 15) * 4;
    int ty4 = (tid >> 4) * 4;
    float o[4][4];
    #pragma unroll
    for (int i = 0; i < 4; i++)
        #pragma unroll
        for (int jj = 0; jj < 4; jj++) o[i][jj] = 0.f;

    for (int kt = 0; kt < L_SEQ / 64; kt++) {
        /* load K transposed and V row-major */
        {
            const float* krow = base + 1024 + (size_t)(kt * 64 + lr) * 3072 + db;
            const float* vrow = base + 2048 + (size_t)(kt * 64 + lr) * 3072 + db;
            #pragma unroll
            for (int v4 = 0; v4 < 4; v4++) {
                float4 kq = *(const float4*)(krow + v4 * 4);
                int d0 = db + v4 * 4;
                Kt[(d0 + 0) * FPAD + lr] = kq.x;
                Kt[(d0 + 1) * FPAD + lr] = kq.y;
                Kt[(d0 + 2) * FPAD + lr] = kq.z;
                Kt[(d0 + 3) * FPAD + lr] = kq.w;
                float4 vq = *(const float4*)(vrow + v4 * 4);
                *(float4*)&Vs[lr * FPAD + d0] = vq;
            }
        }
        __syncthreads();

        /* S = (Q*scale) @ K^T : thread computes rows ty4..+3 x cols tx4..+3 */
        float s[4][4];
        #pragma unroll
        for (int i = 0; i < 4; i++)
            #pragma unroll
            for (int jj = 0; jj < 4; jj++) s[i][jj] = 0.f;
        #pragma unroll 8
        for (int kk = 0; kk < 64; kk++) {
            float4 qf = *(float4*)&Qt[kk * FPAD + ty4];
            float4 kf = *(float4*)&Kt[kk * FPAD + tx4];
            s[0][0] = fmaf(qf.x, kf.x, s[0][0]);
            s[0][1] = fmaf(qf.x, kf.y, s[0][1]);
            s[0][2] = fmaf(qf.x, kf.z, s[0][2]);
            s[0][3] = fmaf(qf.x, kf.w, s[0][3]);
            s[1][0] = fmaf(qf.y, kf.x, s[1][0]);
            s[1][1] = fmaf(qf.y, kf.y, s[1][1]);
            s[1][2] = fmaf(qf.y, kf.z, s[1][2]);
            s[1][3] = fmaf(qf.y, kf.w, s[1][3]);
            s[2][0] = fmaf(qf.z, kf.x, s[2][0]);
            s[2][1] = fmaf(qf.z, kf.y, s[2][1]);
            s[2][2] = fmaf(qf.z, kf.z, s[2][2]);
            s[2][3] = fmaf(qf.z, kf.w, s[2][3]);
            s[3][0] = fmaf(qf.w, kf.x, s[3][0]);
            s[3][1] = fmaf(qf.w, kf.y, s[3][1]);
            s[3][2] = fmaf(qf.w, kf.z, s[3][2]);
            s[3][3] = fmaf(qf.w, kf.w, s[3][3]);
        }
        /* store S transposed: St[c][r] */
        #pragma unroll
        for (int jj = 0; jj < 4; jj++)
            #pragma unroll
            for (int i = 0; i < 4; i++)
                St[(tx4 + jj) * FPAD + ty4 + i] = s[i][jj];
        __syncthreads();

        /* online softmax per query row (64 rows <- threads 0..63) */
        if (tid < 64) {
            int r = tid;
            float mo = m_s[r];
            float mn = mo;
            #pragma unroll 8
            for (int c = 0; c < 64; c++) mn = fmaxf(mn, St[c * FPAD + r]);
            float sc = expf(mo - mn);      /* exp(-inf)=0 on first tile */
            float ls = 0.f;
            #pragma unroll 8
            for (int c = 0; c < 64; c++) {
                float p = __expf(St[c * FPAD + r] - mn);
                St[c * FPAD + r] = p;
                ls += p;
            }
            l_s[r]  = l_s[r] * sc + ls;
            m_s[r]  = mn;
            sc_s[r] = sc;
        }
        __syncthreads();

        /* rescale running O, then O += P @ V */
        float sc0 = sc_s[ty4 + 0], sc1 = sc_s[ty4 + 1];
        float sc2 = sc_s[ty4 + 2], sc3 = sc_s[ty4 + 3];
        #pragma unroll
        for (int jj = 0; jj < 4; jj++) {
            o[0][jj] *= sc0; o[1][jj] *= sc1; o[2][jj] *= sc2; o[3][jj] *= sc3;
        }
        #pragma unroll 8
        for (int c = 0; c < 64; c++) {
            float4 pf = *(float4*)&St[c * FPAD + ty4];
            float4 vf = *(float4*)&Vs[c * FPAD + tx4];
            o[0][0] = fmaf(pf.x, vf.x, o[0][0]);
            o[0][1] = fmaf(pf.x, vf.y, o[0][1]);
            o[0][2] = fmaf(pf.x, vf.z, o[0][2]);
            o[0][3] = fmaf(pf.x, vf.w, o[0][3]);
            o[1][0] = fmaf(pf.y, vf.x, o[1][0]);
            o[1][1] = fmaf(pf.y, vf.y, o[1][1]);
            o[1][2] = fmaf(pf.y, vf.z, o[1][2]);
            o[1][3] = fmaf(pf.y, vf.w, o[1][3]);
            o[2][0] = fmaf(pf.z, vf.x, o[2][0]);
            o[2][1] = fmaf(pf.z, vf.y, o[2][1]);
            o[2][2] = fmaf(pf.z, vf.z, o[2][2]);
            o[2][3] = fmaf(pf.z, vf.w, o[2][3]);
            o[3][0] = fmaf(pf.w, vf.x, o[3][0]);
            o[3][1] = fmaf(pf.w, vf.y, o[3][1]);
            o[3][2] = fmaf(pf.w, vf.z, o[3][2]);
            o[3][3] = fmaf(pf.w, vf.w, o[3][3]);
        }
        __syncthreads();
    }

    /* finalize: divide by l, write out[b, l, h*64+d] */
    float inv0 = 1.f / l_s[ty4 + 0];
    float inv1 = 1.f / l_s[ty4 + 1];
    float inv2 = 1.f / l_s[ty4 + 2];
    float inv3 = 1.f / l_s[ty4 + 3];
    float invs[4] = {inv0, inv1, inv2, inv3};
    #pragma unroll
    for (int i = 0; i < 4; i++) {
        int row = b * L_SEQ + qt * 64 + ty4 + i;
        float* op = out + (size_t)row * D_MODEL + h * 64 + tx4;
        float4 o4;
        o4.x = o[i][0] * invs[i];
        o4.y = o[i][1] * invs[i];
        o4.z = o[i][2] * invs[i];
        o4.w = o[i][3] * invs[i];
        *(float4*)op = o4;
    }
}

/* ---------------- launcher ----------------------------------------------- */
extern "C" void kernel_launch(void* const* d_in, const int* in_sizes, int n_in,
                              void* d_out, int out_size)
{
    const float* x     = (const float*)d_in[0];
    const float* w_qkv = (const float*)d_in[1];
    const float* b_qkv = (const float*)d_in[2];
    const float* w_fc  = (const float*)d_in[3];
    const float* b_fc  = (const float*)d_in[4];
    const float* ln_g  = (const float*)d_in[5];
    const float* ln_b  = (const float*)d_in[6];
    float* out = (float*)d_out;

    float *xn, *qkvp, *attnp;
    cudaGetSymbolAddress((void**)&xn,    g_xn);
    cudaGetSymbolAddress((void**)&qkvp,  g_qkv);
    cudaGetSymbolAddress((void**)&attnp, g_attn);

    /* 1. LayerNorm */
    ln_kernel<<<ROWS, 256>>>(x, ln_g, ln_b, xn);

    /* 2. QKV GEMM: [8192,1024] @ [1024,3072] + bias */
    dim3 g1(3 * D_MODEL / 128, ROWS / 128);
    sgemm_kernel<false><<<g1, 256>>>(xn, w_qkv, b_qkv, nullptr, qkvp,
                                     ROWS, 3 * D_MODEL, D_MODEL);

    /* 3. Flash attention */
    int smem_bytes = (4 * 64 * FPAD + 3 * 64) * (int)sizeof(float); /* ~70 KB */
    cudaFuncSetAttribute(flash_kernel,
                         cudaFuncAttributeMaxDynamicSharedMemorySize, smem_bytes);
    flash_kernel<<<dim3(L_SEQ / 64, NHEADS, BATCH), 256, smem_bytes>>>(qkvp, attnp);

    /* 4. Projection GEMM + bias + residual */
    dim3 g2(D_MODEL / 128, ROWS / 128);
    sgemm_kernel<true><<<g2, 256>>>(attnp, w_fc, b_fc, x, out,
                                    ROWS, D_MODEL, D_MODEL);
}

// round 2
// speedup vs baseline: 2.6342x; 2.6342x over previous
#include <cuda_runtime.h>
#include <math.h>

#define D_MODEL 1024
#define L_SEQ   2048
#define BATCH   4
#define NHEADS  16
#define ROWS    (BATCH * L_SEQ)   /* 8192 */

/* ---------------- scratch (static device globals; no allocations) -------- */
__device__ float g_xn  [ (size_t)ROWS * D_MODEL ];
__device__ float g_qkv [ (size_t)ROWS * 3 * D_MODEL ];
__device__ float g_attn[ (size_t)ROWS * D_MODEL ];
__device__ float g_wq  [ (size_t)D_MODEL * 3 * D_MODEL ];
__device__ float g_wf  [ (size_t)D_MODEL * D_MODEL ];

/* ---------------- helpers ------------------------------------------------ */
__device__ __forceinline__ float to_tf32(float x) {
    float r; asm("cvt.rna.tf32.f32 %0, %1;" : "=f"(r) : "f"(x)); return r;
}
__device__ __forceinline__ unsigned smaddr(const void* p) {
    return (unsigned)__cvta_generic_to_shared(p);
}
__device__ __forceinline__ void cp16(unsigned dst, const void* src) {
    asm volatile("cp.async.cg.shared.global [%0], [%1], 16;\n"
                 :: "r"(dst), "l"(src));
}
__device__ __forceinline__ void mma_tf32(
    float& c0, float& c1, float& c2, float& c3,
    unsigned a0, unsigned a1, unsigned a2, unsigned a3,
    unsigned b0, unsigned b1)
{
    asm volatile(
        "mma.sync.aligned.m16n8k8.row.col.f32.tf32.tf32.f32 "
        "{%0,%1,%2,%3},{%4,%5,%6,%7},{%8,%9},{%0,%1,%2,%3};"
        : "+f"(c0), "+f"(c1), "+f"(c2), "+f"(c3)
        : "r"(a0), "r"(a1), "r"(a2), "r"(a3), "r"(b0), "r"(b1));
}

/* ---------------- tf32 round of weight tensors --------------------------- */
__global__ __launch_bounds__(256) void cvt_kernel(
    const float* __restrict__ in, float* __restrict__ out, int n4)
{
    int i = blockIdx.x * blockDim.x + threadIdx.x;
    if (i < n4) {
        float4 v = ((const float4*)in)[i];
        v.x = to_tf32(v.x); v.y = to_tf32(v.y);
        v.z = to_tf32(v.z); v.w = to_tf32(v.w);
        ((float4*)out)[i] = v;
    }
}

/* ---------------- LayerNorm (writes tf32-rounded xn) --------------------- */
__global__ __launch_bounds__(256) void ln_kernel(
    const float* __restrict__ x, const float* __restrict__ g,
    const float* __restrict__ b, float* __restrict__ out)
{
    int row = blockIdx.x;
    int t   = threadIdx.x;
    const float4* xr = (const float4*)(x + (size_t)row * D_MODEL);
    float4 v = xr[t];
    float s  = v.x + v.y + v.z + v.w;
    float sq = v.x*v.x + v.y*v.y + v.z*v.z + v.w*v.w;

    __shared__ float red0[8], red1[8];
    #pragma unroll
    for (int off = 16; off > 0; off >>= 1) {
        s  += __shfl_down_sync(0xffffffffu, s,  off);
        sq += __shfl_down_sync(0xffffffffu, sq, off);
    }
    int warp = t >> 5, lane = t & 31;
    if (lane == 0) { red0[warp] = s; red1[warp] = sq; }
    __syncthreads();
    if (t < 32) {
        float s2 = (t < 8) ? red0[t] : 0.f;
        float q2 = (t < 8) ? red1[t] : 0.f;
        #pragma unroll
        for (int off = 4; off > 0; off >>= 1) {
            s2 += __shfl_down_sync(0xffffffffu, s2, off);
            q2 += __shfl_down_sync(0xffffffffu, q2, off);
        }
        if (t == 0) {
            float mu  = s2 * (1.0f / D_MODEL);
            float var = q2 * (1.0f / D_MODEL) - mu * mu;
            red0[0] = mu;
            red1[0] = rsqrtf(var + 1e-5f);
        }
    }
    __syncthreads();
    float mu = red0[0], rstd = red1[0];
    float4 gv = ((const float4*)g)[t];
    float4 bv = ((const float4*)b)[t];
    float4 o;
    o.x = to_tf32((v.x - mu) * rstd * gv.x + bv.x);
    o.y = to_tf32((v.y - mu) * rstd * gv.y + bv.y);
    o.z = to_tf32((v.z - mu) * rstd * gv.z + bv.z);
    o.w = to_tf32((v.w - mu) * rstd * gv.w + bv.w);
    ((float4*)(out + (size_t)row * D_MODEL))[t] = o;
}

/* ---------------- tf32 tensor-core GEMM, 128x128x16, cp.async 2-stage ----
   8 warps in 4x2 grid; warp tile 32x64 = 2(m16) x 8(n8) mma tiles.
   A,B inputs must already be tf32-rounded. ------------------------------- */
#define ASTR 20    /* As row stride (floats): conflict-free, 80B = 5*16 */
#define BSTR 132   /* Bs row stride (floats): conflict-free, 528B = 33*16 */

template<bool RES>
__global__ __launch_bounds__(256, 2) void mma_gemm(
    const float* __restrict__ A, const float* __restrict__ B,
    const float* __restrict__ bias, const float* __restrict__ res,
    float* __restrict__ C, int M, int N, int K)
{
    __shared__ float As[2][128 * ASTR];
    __shared__ float Bs[2][16 * BSTR];

    int tid  = threadIdx.x, warp = tid >> 5, lane = tid & 31;
    int g    = lane >> 2,   t4   = lane & 3;
    int wm   = (warp >> 1) * 32, wn = (warp & 1) * 64;
    int brow = blockIdx.y * 128, bcol = blockIdx.x * 128;

    float acc[2][8][4];
    #pragma unroll
    for (int i = 0; i < 2; i++)
        #pragma unroll
        for (int j = 0; j < 8; j++)
            #pragma unroll
            for (int c = 0; c < 4; c++) acc[i][j][c] = 0.f;

    int ar = tid >> 1, ak = (tid & 1) * 8;   /* A tile: row, k-chunk base */
    int bk = tid >> 4, bn = (tid & 15) * 8;  /* B tile: k row, n-chunk base */
    const float* Ag = A + (size_t)(brow + ar) * K + ak;
    const float* Bg = B + (size_t)bk * N + bcol + bn;
    unsigned aS[2] = { smaddr(&As[0][ar * ASTR + ak]),
                       smaddr(&As[1][ar * ASTR + ak]) };
    unsigned bS[2] = { smaddr(&Bs[0][bk * BSTR + bn]),
                       smaddr(&Bs[1][bk * BSTR + bn]) };

    /* prefetch iter 0 */
    cp16(aS[0],      Ag);     cp16(aS[0] + 16, Ag + 4);
    cp16(bS[0],      Bg);     cp16(bS[0] + 16, Bg + 4);
    asm volatile("cp.async.commit_group;");

    int nit = K / 16;
    for (int it = 0; it < nit; it++) {
        if (it + 1 < nit) {
            int buf = (it + 1) & 1;
            int k0  = (it + 1) * 16;
            cp16(aS[buf],      Ag + k0);
            cp16(aS[buf] + 16, Ag + k0 + 4);
            cp16(bS[buf],      Bg + (size_t)k0 * N);
            cp16(bS[buf] + 16, Bg + (size_t)k0 * N + 4);
        }
        asm volatile("cp.async.commit_group;");
        asm volatile("cp.async.wait_group 1;");
        __syncthreads();

        const float* as = As[it & 1];
        const float* bs = Bs[it & 1];
        #pragma unroll
        for (int ks = 0; ks < 2; ks++) {
            int kc = ks * 8;
            unsigned a[2][4];
            #pragma unroll
            for (int i = 0; i < 2; i++) {
                int r0 = wm + 16 * i + g;
                a[i][0] = __float_as_uint(as[(r0    ) * ASTR + kc + t4    ]);
                a[i][1] = __float_as_uint(as[(r0 + 8) * ASTR + kc + t4    ]);
                a[i][2] = __float_as_uint(as[(r0    ) * ASTR + kc + t4 + 4]);
                a[i][3] = __float_as_uint(as[(r0 + 8) * ASTR + kc + t4 + 4]);
            }
            #pragma unroll
            for (int j = 0; j < 8; j++) {
                unsigned b0 = __float_as_uint(bs[(kc + t4    ) * BSTR + wn + 8*j + g]);
                unsigned b1 = __float_as_uint(bs[(kc + t4 + 4) * BSTR + wn + 8*j + g]);
                mma_tf32(acc[0][j][0], acc[0][j][1], acc[0][j][2], acc[0][j][3],
                         a[0][0], a[0][1], a[0][2], a[0][3], b0, b1);
                mma_tf32(acc[1][j][0], acc[1][j][1], acc[1][j][2], acc[1][j][3],
                         a[1][0], a[1][1], a[1][2], a[1][3], b0, b1);
            }
        }
        __syncthreads();
    }

    /* epilogue: bias (+ residual) fused, float2 stores */
    #pragma unroll
    for (int j = 0; j < 8; j++) {
        int col = bcol + wn + 8 * j + 2 * t4;
        float2 bi = *(const float2*)&bias[col];
        #pragma unroll
        for (int i = 0; i < 2; i++) {
            int r0 = brow + wm + 16 * i + g;
            float2 v0 = { acc[i][j][0] + bi.x, acc[i][j][1] + bi.y };
            float2 v1 = { acc[i][j][2] + bi.x, acc[i][j][3] + bi.y };
            if (RES) {
                float2 ra = *(const float2*)&res[(size_t)(r0    ) * N + col];
                float2 rb = *(const float2*)&res[(size_t)(r0 + 8) * N + col];
                v0.x += ra.x; v0.y += ra.y;
                v1.x += rb.x; v1.y += rb.y;
            }
            *(float2*)&C[(size_t)(r0    ) * N + col] = v0;
            *(float2*)&C[(size_t)(r0 + 8) * N + col] = v1;
        }
    }
}

/* ---------------- flash attention with tf32 mma, BR=128, BC=64 -----------
   8 warps, each owns 16 query rows -> softmax fully warp-local (shfl.bfly).
   P roundtrips smem within its own warp only (__syncwarp). -------------- */
#define QS 68   /* smem row stride for 64-wide tiles */

__global__ __launch_bounds__(256) void flash_mma(
    const float* __restrict__ qkv, float* __restrict__ out)
{
    extern __shared__ float sm[];
    float* Qs = sm;                 /* [128][QS] tf32, pre-scaled */
    float* Ks = Qs + 128 * QS;      /* [64][QS]  row n, col k(=d) */
    float* Vs = Ks + 64 * QS;       /* [64][QS]  row k(=c), col n(=d) */
    float* Ps = Vs + 64 * QS;       /* [128][QS] */

    int qt = blockIdx.x, h = blockIdx.y, b = blockIdx.z;
    int tid = threadIdx.x, warp = tid >> 5, lane = tid & 31;
    int g = lane >> 2, t4 = lane & 3;
    const float scale = 0.125f;     /* 1/sqrt(64) */
    const float* base = qkv + (size_t)b * L_SEQ * 3072 + h * 64;

    /* load Q tile (rows qt*128..+127), tf32-rounded, pre-scaled */
    for (int idx = tid; idx < 128 * 16; idx += 256) {
        int r = idx >> 4, c4 = (idx & 15) * 4;
        float4 q = *(const float4*)(base + (size_t)(qt * 128 + r) * 3072 + c4);
        float* d = &Qs[r * QS + c4];
        d[0] = to_tf32(q.x * scale); d[1] = to_tf32(q.y * scale);
        d[2] = to_tf32(q.z * scale); d[3] = to_tf32(q.w * scale);
    }

    float ofr[8][4];
    #pragma unroll
    for (int j = 0; j < 8; j++)
        #pragma unroll
        for (int c = 0; c < 4; c++) ofr[j][c] = 0.f;
    float m_lo = -INFINITY, m_hi = -INFINITY, l_lo = 0.f, l_hi = 0.f;

    int rlo = warp * 16 + g;        /* this thread's low row in tile */

    for (int kt = 0; kt < L_SEQ / 64; kt++) {
        __syncthreads();            /* protect Ks/Vs from prev-iter readers */
        for (int idx = tid; idx < 64 * 16; idx += 256) {
            int r = idx >> 4, c4 = (idx & 15) * 4;
            const float* kp = base + 1024 + (size_t)(kt * 64 + r) * 3072 + c4;
            float4 kv = *(const float4*)kp;
            float4 vv = *(const float4*)(kp + 1024);
            float* dk = &Ks[r * QS + c4];
            float* dv = &Vs[r * QS + c4];
            dk[0] = to_tf32(kv.x); dk[1] = to_tf32(kv.y);
            dk[2] = to_tf32(kv.z); dk[3] = to_tf32(kv.w);
            dv[0] = to_tf32(vv.x); dv[1] = to_tf32(vv.y);
            dv[2] = to_tf32(vv.z); dv[3] = to_tf32(vv.w);
        }
        __syncthreads();

        /* S = Q @ K^T : warp computes rows rlo(+8) x all 64 cols */
        float sfr[8][4];
        #pragma unroll
        for (int j = 0; j < 8; j++)
            #pragma unroll
            for (int c = 0; c < 4; c++) sfr[j][c] = 0.f;
        #pragma unroll
        for (int ks = 0; ks < 8; ks++) {
            int kc = ks * 8;
            unsigned a0 = __float_as_uint(Qs[(rlo    ) * QS + kc + t4    ]);
            unsigned a1 = __float_as_uint(Qs[(rlo + 8) * QS + kc + t4    ]);
            unsigned a2 = __float_as_uint(Qs[(rlo    ) * QS + kc + t4 + 4]);
            unsigned a3 = __float_as_uint(Qs[(rlo + 8) * QS + kc + t4 + 4]);
            #pragma unroll
            for (int j = 0; j < 8; j++) {
                unsigned b0 = __float_as_uint(Ks[(8*j + g) * QS + kc + t4    ]);
                unsigned b1 = __float_as_uint(Ks[(8*j + g) * QS + kc + t4 + 4]);
                mma_tf32(sfr[j][0], sfr[j][1], sfr[j][2], sfr[j][3],
                         a0, a1, a2, a3, b0, b1);
            }
        }

        /* warp-local online softmax (rows rlo and rlo+8) */
        float mx_lo = -INFINITY, mx_hi = -INFINITY;
        #pragma unroll
        for (int j = 0; j < 8; j++) {
            mx_lo = fmaxf(mx_lo, fmaxf(sfr[j][0], sfr[j][1]));
            mx_hi = fmaxf(mx_hi, fmaxf(sfr[j][2], sfr[j][3]));
        }
        mx_lo = fmaxf(mx_lo, __shfl_xor_sync(0xffffffffu, mx_lo, 1));
        mx_lo = fmaxf(mx_lo, __shfl_xor_sync(0xffffffffu, mx_lo, 2));
        mx_hi = fmaxf(mx_hi, __shfl_xor_sync(0xffffffffu, mx_hi, 1));
        mx_hi = fmaxf(mx_hi, __shfl_xor_sync(0xffffffffu, mx_hi, 2));
        float mn_lo = fmaxf(m_lo, mx_lo), mn_hi = fmaxf(m_hi, mx_hi);
        float sc_lo = __expf(m_lo - mn_lo), sc_hi = __expf(m_hi - mn_hi);
        float sum_lo = 0.f, sum_hi = 0.f;
        #pragma unroll
        for (int j = 0; j < 8; j++) {
            float p0 = __expf(sfr[j][0] - mn_lo);
            float p1 = __expf(sfr[j][1] - mn_lo);
            float p2 = __expf(sfr[j][2] - mn_hi);
            float p3 = __expf(sfr[j][3] - mn_hi);
            sum_lo += p0 + p1; sum_hi += p2 + p3;
            float2* plo = (float2*)&Ps[(rlo    ) * QS + 8*j + 2*t4];
            float2* phi = (float2*)&Ps[(rlo + 8) * QS + 8*j + 2*t4];
            *plo = make_float2(to_tf32(p0), to_tf32(p1));
            *phi = make_float2(to_tf32(p2), to_tf32(p3));
        }
        sum_lo += __shfl_xor_sync(0xffffffffu, sum_lo, 1);
        sum_lo += __shfl_xor_sync(0xffffffffu, sum_lo, 2);
        sum_hi += __shfl_xor_sync(0xffffffffu, sum_hi, 1);
        sum_hi += __shfl_xor_sync(0xffffffffu, sum_hi, 2);
        l_lo = l_lo * sc_lo + sum_lo; m_lo = mn_lo;
        l_hi = l_hi * sc_hi + sum_hi; m_hi = mn_hi;
        #pragma unroll
        for (int j = 0; j < 8; j++) {
            ofr[j][0] *= sc_lo; ofr[j][1] *= sc_lo;
            ofr[j][2] *= sc_hi; ofr[j][3] *= sc_hi;
        }
        __syncwarp();   /* P stores visible to all lanes of this warp */

        /* O += P @ V */
        #pragma unroll
        for (int ks = 0; ks < 8; ks++) {
            int kc = ks * 8;
            unsigned a0 = __float_as_uint(Ps[(rlo    ) * QS + kc + t4    ]);
            unsigned a1 = __float_as_uint(Ps[(rlo + 8) * QS + kc + t4    ]);
            unsigned a2 = __float_as_uint(Ps[(rlo    ) * QS + kc + t4 + 4]);
            unsigned a3 = __float_as_uint(Ps[(rlo + 8) * QS + kc + t4 + 4]);
            #pragma unroll
            for (int j = 0; j < 8; j++) {
                unsigned b0 = __float_as_uint(Vs[(kc + t4    ) * QS + 8*j + g]);
                unsigned b1 = __float_as_uint(Vs[(kc + t4 + 4) * QS + 8*j + g]);
                mma_tf32(ofr[j][0], ofr[j][1], ofr[j][2], ofr[j][3],
                         a0, a1, a2, a3, b0, b1);
            }
        }
    }

    /* finalize: O /= l, tf32-round (input of proj GEMM), write */
    float inv_lo = 1.f / l_lo, inv_hi = 1.f / l_hi;
    int row_lo = b * L_SEQ + qt * 128 + warp * 16 + g;
    #pragma unroll
    for (int j = 0; j < 8; j++) {
        int col = h * 64 + 8 * j + 2 * t4;
        float2 v0 = make_float2(to_tf32(ofr[j][0] * inv_lo),
                                to_tf32(ofr[j][1] * inv_lo));
        float2 v1 = make_float2(to_tf32(ofr[j][2] * inv_hi),
                                to_tf32(ofr[j][3] * inv_hi));
        *(float2*)&out[(size_t)(row_lo    ) * D_MODEL + col] = v0;
        *(float2*)&out[(size_t)(row_lo + 8) * D_MODEL + col] = v1;
    }
}

/* ---------------- launcher ----------------------------------------------- */
extern "C" void kernel_launch(void* const* d_in, const int* in_sizes, int n_in,
                              void* d_out, int out_size)
{
    const float* x     = (const float*)d_in[0];
    const float* w_qkv = (const float*)d_in[1];
    const float* b_qkv = (const float*)d_in[2];
    const float* w_fc  = (const float*)d_in[3];
    const float* b_fc  = (const float*)d_in[4];
    const float* ln_g  = (const float*)d_in[5];
    const float* ln_b  = (const float*)d_in[6];
    float* out = (float*)d_out;

    float *xn, *qkvp, *attnp, *wq, *wf;
    cudaGetSymbolAddress((void**)&xn,    g_xn);
    cudaGetSymbolAddress((void**)&qkvp,  g_qkv);
    cudaGetSymbolAddress((void**)&attnp, g_attn);
    cudaGetSymbolAddress((void**)&wq,    g_wq);
    cudaGetSymbolAddress((void**)&wf,    g_wf);

    /* 0. round weights to tf32 */
    cvt_kernel<<<(D_MODEL*3*D_MODEL/4 + 255)/256, 256>>>(w_qkv, wq, D_MODEL*3*D_MODEL/4);
    cvt_kernel<<<(D_MODEL*D_MODEL/4   + 255)/256, 256>>>(w_fc,  wf, D_MODEL*D_MODEL/4);

    /* 1. LayerNorm (tf32-rounded output) */
    ln_kernel<<<ROWS, 256>>>(x, ln_g, ln_b, xn);

    /* 2. QKV GEMM: [8192,1024] @ [1024,3072] + bias */
    dim3 g1(3 * D_MODEL / 128, ROWS / 128);
    mma_gemm<false><<<g1, 256>>>(xn, wq, b_qkv, nullptr, qkvp,
                                 ROWS, 3 * D_MODEL, D_MODEL);

    /* 3. Flash attention (tensor-core) */
    int smem_bytes = 384 * QS * (int)sizeof(float);   /* 104448 B */
    cudaFuncSetAttribute(flash_mma,
                         cudaFuncAttributeMaxDynamicSharedMemorySize, smem_bytes);
    flash_mma<<<dim3(L_SEQ / 128, NHEADS, BATCH), 256, smem_bytes>>>(qkvp, attnp);

    /* 4. Projection GEMM + bias + residual */
    dim3 g2(D_MODEL / 128, ROWS / 128);
    mma_gemm<true><<<g2, 256>>>(attnp, wf, b_fc, x, out,
                                ROWS, D_MODEL, D_MODEL);
}

// round 3
// speedup vs baseline: 2.6397x; 1.0021x over previous
#include <cuda_runtime.h>
#include <math.h>

#define D_MODEL 1024
#define L_SEQ   2048
#define BATCH   4
#define NHEADS  16
#define ROWS    (BATCH * L_SEQ)   /* 8192 */

/* ---------------- scratch (static device globals; no allocations) -------- */
__device__ float g_xn  [ (size_t)ROWS * D_MODEL ];
__device__ float g_qkv [ (size_t)ROWS * 3 * D_MODEL ];
__device__ float g_attn[ (size_t)ROWS * D_MODEL ];
__device__ float g_wq  [ (size_t)D_MODEL * 3 * D_MODEL ];
__device__ float g_wf  [ (size_t)D_MODEL * D_MODEL ];

/* ---------------- helpers ------------------------------------------------ */
__device__ __forceinline__ float to_tf32(float x) {
    float r; asm("cvt.rna.tf32.f32 %0, %1;" : "=f"(r) : "f"(x)); return r;
}
__device__ __forceinline__ unsigned smaddr(const void* p) {
    return (unsigned)__cvta_generic_to_shared(p);
}
__device__ __forceinline__ void cp16(unsigned dst, const void* src) {
    asm volatile("cp.async.cg.shared.global [%0], [%1], 16;\n"
                 :: "r"(dst), "l"(src));
}
__device__ __forceinline__ void mma_tf32(
    float& c0, float& c1, float& c2, float& c3,
    unsigned a0, unsigned a1, unsigned a2, unsigned a3,
    unsigned b0, unsigned b1)
{
    asm volatile(
        "mma.sync.aligned.m16n8k8.row.col.f32.tf32.tf32.f32 "
        "{%0,%1,%2,%3},{%4,%5,%6,%7},{%8,%9},{%0,%1,%2,%3};"
        : "+f"(c0), "+f"(c1), "+f"(c2), "+f"(c3)
        : "r"(a0), "r"(a1), "r"(a2), "r"(a3), "r"(b0), "r"(b1));
}

/* ---------------- tf32 round of weight tensors --------------------------- */
__global__ __launch_bounds__(256) void cvt_kernel(
    const float* __restrict__ in, float* __restrict__ out, int n4)
{
    int i = blockIdx.x * blockDim.x + threadIdx.x;
    if (i < n4) {
        float4 v = ((const float4*)in)[i];
        v.x = to_tf32(v.x); v.y = to_tf32(v.y);
        v.z = to_tf32(v.z); v.w = to_tf32(v.w);
        ((float4*)out)[i] = v;
    }
}

/* ---------------- LayerNorm (writes tf32-rounded xn) --------------------- */
__global__ __launch_bounds__(256) void ln_kernel(
    const float* __restrict__ x, const float* __restrict__ g,
    const float* __restrict__ b, float* __restrict__ out)
{
    int row = blockIdx.x;
    int t   = threadIdx.x;
    const float4* xr = (const float4*)(x + (size_t)row * D_MODEL);
    float4 v = xr[t];
    float s  = v.x + v.y + v.z + v.w;
    float sq = v.x*v.x + v.y*v.y + v.z*v.z + v.w*v.w;

    __shared__ float red0[8], red1[8];
    #pragma unroll
    for (int off = 16; off > 0; off >>= 1) {
        s  += __shfl_down_sync(0xffffffffu, s,  off);
        sq += __shfl_down_sync(0xffffffffu, sq, off);
    }
    int warp = t >> 5, lane = t & 31;
    if (lane == 0) { red0[warp] = s; red1[warp] = sq; }
    __syncthreads();
    if (t < 32) {
        float s2 = (t < 8) ? red0[t] : 0.f;
        float q2 = (t < 8) ? red1[t] : 0.f;
        #pragma unroll
        for (int off = 4; off > 0; off >>= 1) {
            s2 += __shfl_down_sync(0xffffffffu, s2, off);
            q2 += __shfl_down_sync(0xffffffffu, q2, off);
        }
        if (t == 0) {
            float mu  = s2 * (1.0f / D_MODEL);
            float var = q2 * (1.0f / D_MODEL) - mu * mu;
            red0[0] = mu;
            red1[0] = rsqrtf(var + 1e-5f);
        }
    }
    __syncthreads();
    float mu = red0[0], rstd = red1[0];
    float4 gv = ((const float4*)g)[t];
    float4 bv = ((const float4*)b)[t];
    float4 o;
    o.x = to_tf32((v.x - mu) * rstd * gv.x + bv.x);
    o.y = to_tf32((v.y - mu) * rstd * gv.y + bv.y);
    o.z = to_tf32((v.z - mu) * rstd * gv.z + bv.z);
    o.w = to_tf32((v.w - mu) * rstd * gv.w + bv.w);
    ((float4*)(out + (size_t)row * D_MODEL))[t] = o;
}

/* ---------------- tf32 tensor-core GEMM, 128x128x16, cp.async 2-stage ----
   8 warps in 4x2 grid; warp tile 32x64 = 2(m16) x 8(n8) mma tiles.
   A,B inputs must already be tf32-rounded. ------------------------------- */
#define ASTR 20    /* As row stride (floats): conflict-free, 80B = 5*16 */
#define BSTR 132   /* Bs row stride (floats): conflict-free, 528B = 33*16 */

template<bool RES>
__global__ __launch_bounds__(256, 2) void mma_gemm(
    const float* __restrict__ A, const float* __restrict__ B,
    const float* __restrict__ bias, const float* __restrict__ res,
    float* __restrict__ C, int M, int N, int K)
{
    __shared__ float As[2][128 * ASTR];
    __shared__ float Bs[2][16 * BSTR];

    int tid  = threadIdx.x, warp = tid >> 5, lane = tid & 31;
    int g    = lane >> 2,   t4   = lane & 3;
    int wm   = (warp >> 1) * 32, wn = (warp & 1) * 64;
    int brow = blockIdx.y * 128, bcol = blockIdx.x * 128;

    float acc[2][8][4];
    #pragma unroll
    for (int i = 0; i < 2; i++)
        #pragma unroll
        for (int j = 0; j < 8; j++)
            #pragma unroll
            for (int c = 0; c < 4; c++) acc[i][j][c] = 0.f;

    int ar = tid >> 1, ak = (tid & 1) * 8;   /* A tile: row, k-chunk base */
    int bk = tid >> 4, bn = (tid & 15) * 8;  /* B tile: k row, n-chunk base */
    const float* Ag = A + (size_t)(brow + ar) * K + ak;
    const float* Bg = B + (size_t)bk * N + bcol + bn;
    unsigned aS[2] = { smaddr(&As[0][ar * ASTR + ak]),
                       smaddr(&As[1][ar * ASTR + ak]) };
    unsigned bS[2] = { smaddr(&Bs[0][bk * BSTR + bn]),
                       smaddr(&Bs[1][bk * BSTR + bn]) };

    /* prefetch iter 0 */
    cp16(aS[0],      Ag);     cp16(aS[0] + 16, Ag + 4);
    cp16(bS[0],      Bg);     cp16(bS[0] + 16, Bg + 4);
    asm volatile("cp.async.commit_group;");

    int nit = K / 16;
    for (int it = 0; it < nit; it++) {
        if (it + 1 < nit) {
            int buf = (it + 1) & 1;
            int k0  = (it + 1) * 16;
            cp16(aS[buf],      Ag + k0);
            cp16(aS[buf] + 16, Ag + k0 + 4);
            cp16(bS[buf],      Bg + (size_t)k0 * N);
            cp16(bS[buf] + 16, Bg + (size_t)k0 * N + 4);
        }
        asm volatile("cp.async.commit_group;");
        asm volatile("cp.async.wait_group 1;");
        __syncthreads();

        const float* as = As[it & 1];
        const float* bs = Bs[it & 1];
        #pragma unroll
        for (int ks = 0; ks < 2; ks++) {
            int kc = ks * 8;
            unsigned a[2][4];
            #pragma unroll
            for (int i = 0; i < 2; i++) {
                int r0 = wm + 16 * i + g;
                a[i][0] = __float_as_uint(as[(r0    ) * ASTR + kc + t4    ]);
                a[i][1] = __float_as_uint(as[(r0 + 8) * ASTR + kc + t4    ]);
                a[i][2] = __float_as_uint(as[(r0    ) * ASTR + kc + t4 + 4]);
                a[i][3] = __float_as_uint(as[(r0 + 8) * ASTR + kc + t4 + 4]);
            }
            #pragma unroll
            for (int j = 0; j < 8; j++) {
                unsigned b0 = __float_as_uint(bs[(kc + t4    ) * BSTR + wn + 8*j + g]);
                unsigned b1 = __float_as_uint(bs[(kc + t4 + 4) * BSTR + wn + 8*j + g]);
                mma_tf32(acc[0][j][0], acc[0][j][1], acc[0][j][2], acc[0][j][3],
                         a[0][0], a[0][1], a[0][2], a[0][3], b0, b1);
                mma_tf32(acc[1][j][0], acc[1][j][1], acc[1][j][2], acc[1][j][3],
                         a[1][0], a[1][1], a[1][2], a[1][3], b0, b1);
            }
        }
        __syncthreads();
    }

    /* epilogue: bias (+ residual) fused, float2 stores */
    #pragma unroll
    for (int j = 0; j < 8; j++) {
        int col = bcol + wn + 8 * j + 2 * t4;
        float2 bi = *(const float2*)&bias[col];
        #pragma unroll
        for (int i = 0; i < 2; i++) {
            int r0 = brow + wm + 16 * i + g;
            float2 v0 = { acc[i][j][0] + bi.x, acc[i][j][1] + bi.y };
            float2 v1 = { acc[i][j][2] + bi.x, acc[i][j][3] + bi.y };
            if (RES) {
                float2 ra = *(const float2*)&res[(size_t)(r0    ) * N + col];
                float2 rb = *(const float2*)&res[(size_t)(r0 + 8) * N + col];
                v0.x += ra.x; v0.y += ra.y;
                v1.x += rb.x; v1.y += rb.y;
            }
            *(float2*)&C[(size_t)(r0    ) * N + col] = v0;
            *(float2*)&C[(size_t)(r0 + 8) * N + col] = v1;
        }
    }
}

/* ---------------- flash attention with tf32 mma, BR=128, BC=64 -----------
   8 warps, each owns 16 query rows -> softmax fully warp-local (shfl.bfly).
   P roundtrips smem within its own warp only (__syncwarp). -------------- */
#define QS 68   /* smem row stride for 64-wide tiles */

__global__ __launch_bounds__(256) void flash_mma(
    const float* __restrict__ qkv, float* __restrict__ out)
{
    extern __shared__ float sm[];
    float* Qs = sm;                 /* [128][QS] tf32, pre-scaled */
    float* Ks = Qs + 128 * QS;      /* [64][QS]  row n, col k(=d) */
    float* Vs = Ks + 64 * QS;       /* [64][QS]  row k(=c), col n(=d) */
    float* Ps = Vs + 64 * QS;       /* [128][QS] */

    int qt = blockIdx.x, h = blockIdx.y, b = blockIdx.z;
    int tid = threadIdx.x, warp = tid >> 5, lane = tid & 31;
    int g = lane >> 2, t4 = lane & 3;
    const float scale = 0.125f;     /* 1/sqrt(64) */
    const float* base = qkv + (size_t)b * L_SEQ * 3072 + h * 64;

    /* load Q tile (rows qt*128..+127), tf32-rounded, pre-scaled */
    for (int idx = tid; idx < 128 * 16; idx += 256) {
        int r = idx >> 4, c4 = (idx & 15) * 4;
        float4 q = *(const float4*)(base + (size_t)(qt * 128 + r) * 3072 + c4);
        float* d = &Qs[r * QS + c4];
        d[0] = to_tf32(q.x * scale); d[1] = to_tf32(q.y * scale);
        d[2] = to_tf32(q.z * scale); d[3] = to_tf32(q.w * scale);
    }

    float ofr[8][4];
    #pragma unroll
    for (int j = 0; j < 8; j++)
        #pragma unroll
        for (int c = 0; c < 4; c++) ofr[j][c] = 0.f;
    float m_lo = -INFINITY, m_hi = -INFINITY, l_lo = 0.f, l_hi = 0.f;

    int rlo = warp * 16 + g;        /* this thread's low row in tile */

    for (int kt = 0; kt < L_SEQ / 64; kt++) {
        __syncthreads();            /* protect Ks/Vs from prev-iter readers */
        for (int idx = tid; idx < 64 * 16; idx += 256) {
            int r = idx >> 4, c4 = (idx & 15) * 4;
            const float* kp = base + 1024 + (size_t)(kt * 64 + r) * 3072 + c4;
            float4 kv = *(const float4*)kp;
            float4 vv = *(const float4*)(kp + 1024);
            float* dk = &Ks[r * QS + c4];
            float* dv = &Vs[r * QS + c4];
            dk[0] = to_tf32(kv.x); dk[1] = to_tf32(kv.y);
            dk[2] = to_tf32(kv.z); dk[3] = to_tf32(kv.w);
            dv[0] = to_tf32(vv.x); dv[1] = to_tf32(vv.y);
            dv[2] = to_tf32(vv.z); dv[3] = to_tf32(vv.w);
        }
        __syncthreads();

        /* S = Q @ K^T : warp computes rows rlo(+8) x all 64 cols */
        float sfr[8][4];
        #pragma unroll
        for (int j = 0; j < 8; j++)
            #pragma unroll
            for (int c = 0; c < 4; c++) sfr[j][c] = 0.f;
        #pragma unroll
        for (int ks = 0; ks < 8; ks++) {
            int kc = ks * 8;
            unsigned a0 = __float_as_uint(Qs[(rlo    ) * QS + kc + t4    ]);
            unsigned a1 = __float_as_uint(Qs[(rlo + 8) * QS + kc + t4    ]);
            unsigned a2 = __float_as_uint(Qs[(rlo    ) * QS + kc + t4 + 4]);
            unsigned a3 = __float_as_uint(Qs[(rlo + 8) * QS + kc + t4 + 4]);
            #pragma unroll
            for (int j = 0; j < 8; j++) {
                unsigned b0 = __float_as_uint(Ks[(8*j + g) * QS + kc + t4    ]);
                unsigned b1 = __float_as_uint(Ks[(8*j + g) * QS + kc + t4 + 4]);
                mma_tf32(sfr[j][0], sfr[j][1], sfr[j][2], sfr[j][3],
                         a0, a1, a2, a3, b0, b1);
            }
        }

        /* warp-local online softmax (rows rlo and rlo+8) */
        float mx_lo = -INFINITY, mx_hi = -INFINITY;
        #pragma unroll
        for (int j = 0; j < 8; j++) {
            mx_lo = fmaxf(mx_lo, fmaxf(sfr[j][0], sfr[j][1]));
            mx_hi = fmaxf(mx_hi, fmaxf(sfr[j][2], sfr[j][3]));
        }
        mx_lo = fmaxf(mx_lo, __shfl_xor_sync(0xffffffffu, mx_lo, 1));
        mx_lo = fmaxf(mx_lo, __shfl_xor_sync(0xffffffffu, mx_lo, 2));
        mx_hi = fmaxf(mx_hi, __shfl_xor_sync(0xffffffffu, mx_hi, 1));
        mx_hi = fmaxf(mx_hi, __shfl_xor_sync(0xffffffffu, mx_hi, 2));
        float mn_lo = fmaxf(m_lo, mx_lo), mn_hi = fmaxf(m_hi, mx_hi);
        float sc_lo = __expf(m_lo - mn_lo), sc_hi = __expf(m_hi - mn_hi);
        float sum_lo = 0.f, sum_hi = 0.f;
        #pragma unroll
        for (int j = 0; j < 8; j++) {
            float p0 = __expf(sfr[j][0] - mn_lo);
            float p1 = __expf(sfr[j][1] - mn_lo);
            float p2 = __expf(sfr[j][2] - mn_hi);
            float p3 = __expf(sfr[j][3] - mn_hi);
            sum_lo += p0 + p1; sum_hi += p2 + p3;
            float2* plo = (float2*)&Ps[(rlo    ) * QS + 8*j + 2*t4];
            float2* phi = (float2*)&Ps[(rlo + 8) * QS + 8*j + 2*t4];
            *plo = make_float2(to_tf32(p0), to_tf32(p1));
            *phi = make_float2(to_tf32(p2), to_tf32(p3));
        }
        sum_lo += __shfl_xor_sync(0xffffffffu, sum_lo, 1);
        sum_lo += __shfl_xor_sync(0xffffffffu, sum_lo, 2);
        sum_hi += __shfl_xor_sync(0xffffffffu, sum_hi, 1);
        sum_hi += __shfl_xor_sync(0xffffffffu, sum_hi, 2);
        l_lo = l_lo * sc_lo + sum_lo; m_lo = mn_lo;
        l_hi = l_hi * sc_hi + sum_hi; m_hi = mn_hi;
        #pragma unroll
        for (int j = 0; j < 8; j++) {
            ofr[j][0] *= sc_lo; ofr[j][1] *= sc_lo;
            ofr[j][2] *= sc_hi; ofr[j][3] *= sc_hi;
        }
        __syncwarp();   /* P stores visible to all lanes of this warp */

        /* O += P @ V */
        #pragma unroll
        for (int ks = 0; ks < 8; ks++) {
            int kc = ks * 8;
            unsigned a0 = __float_as_uint(Ps[(rlo    ) * QS + kc + t4    ]);
            unsigned a1 = __float_as_uint(Ps[(rlo + 8) * QS + kc + t4    ]);
            unsigned a2 = __float_as_uint(Ps[(rlo    ) * QS + kc + t4 + 4]);
            unsigned a3 = __float_as_uint(Ps[(rlo + 8) * QS + kc + t4 + 4]);
            #pragma unroll
            for (int j = 0; j < 8; j++) {
                unsigned b0 = __float_as_uint(Vs[(kc + t4    ) * QS + 8*j + g]);
                unsigned b1 = __float_as_uint(Vs[(kc + t4 + 4) * QS + 8*j + g]);
                mma_tf32(ofr[j][0], ofr[j][1], ofr[j][2], ofr[j][3],
                         a0, a1, a2, a3, b0, b1);
            }
        }
    }

    /* finalize: O /= l, tf32-round (input of proj GEMM), write */
    float inv_lo = 1.f / l_lo, inv_hi = 1.f / l_hi;
    int row_lo = b * L_SEQ + qt * 128 + warp * 16 + g;
    #pragma unroll
    for (int j = 0; j < 8; j++) {
        int col = h * 64 + 8 * j + 2 * t4;
        float2 v0 = make_float2(to_tf32(ofr[j][0] * inv_lo),
                                to_tf32(ofr[j][1] * inv_lo));
        float2 v1 = make_float2(to_tf32(ofr[j][2] * inv_hi),
                                to_tf32(ofr[j][3] * inv_hi));
        *(float2*)&out[(size_t)(row_lo    ) * D_MODEL + col] = v0;
        *(float2*)&out[(size_t)(row_lo + 8) * D_MODEL + col] = v1;
    }
}

/* ---------------- launcher ----------------------------------------------- */
extern "C" void kernel_launch(void* const* d_in, const int* in_sizes, int n_in,
                              void* d_out, int out_size)
{
    const float* x     = (const float*)d_in[0];
    const float* w_qkv = (const float*)d_in[1];
    const float* b_qkv = (const float*)d_in[2];
    const float* w_fc  = (const float*)d_in[3];
    const float* b_fc  = (const float*)d_in[4];
    const float* ln_g  = (const float*)d_in[5];
    const float* ln_b  = (const float*)d_in[6];
    float* out = (float*)d_out;

    float *xn, *qkvp, *attnp, *wq, *wf;
    cudaGetSymbolAddress((void**)&xn,    g_xn);
    cudaGetSymbolAddress((void**)&qkvp,  g_qkv);
    cudaGetSymbolAddress((void**)&attnp, g_attn);
    cudaGetSymbolAddress((void**)&wq,    g_wq);
    cudaGetSymbolAddress((void**)&wf,    g_wf);

    /* 0. round weights to tf32 */
    cvt_kernel<<<(D_MODEL*3*D_MODEL/4 + 255)/256, 256>>>(w_qkv, wq, D_MODEL*3*D_MODEL/4);
    cvt_kernel<<<(D_MODEL*D_MODEL/4   + 255)/256, 256>>>(w_fc,  wf, D_MODEL*D_MODEL/4);

    /* 1. LayerNorm (tf32-rounded output) */
    ln_kernel<<<ROWS, 256>>>(x, ln_g, ln_b, xn);

    /* 2. QKV GEMM: [8192,1024] @ [1024,3072] + bias */
    dim3 g1(3 * D_MODEL / 128, ROWS / 128);
    mma_gemm<false><<<g1, 256>>>(xn, wq, b_qkv, nullptr, qkvp,
                                 ROWS, 3 * D_MODEL, D_MODEL);

    /* 3. Flash attention (tensor-core) */
    int smem_bytes = 384 * QS * (int)sizeof(float);   /* 104448 B */
    cudaFuncSetAttribute(flash_mma,
                         cudaFuncAttributeMaxDynamicSharedMemorySize, smem_bytes);
    flash_mma<<<dim3(L_SEQ / 128, NHEADS, BATCH), 256, smem_bytes>>>(qkvp, attnp);

    /* 4. Projection GEMM + bias + residual */
    dim3 g2(D_MODEL / 128, ROWS / 128);
    mma_gemm<true><<<g2, 256>>>(attnp, wf, b_fc, x, out,
                                ROWS, D_MODEL, D_MODEL);
}